// round 12
// baseline (speedup 1.0000x reference)
#include <cuda_runtime.h>
#include <cuda_fp16.h>
#include <math.h>
#include <stdint.h>

#define BATCH 32
#define SEQ   2048
#define DIM   512
#define DADIM 512
#define NLDIM 512

// ---------------- fp16 scratch (static, allocation-free) ----------------
__device__ __half g_xh [(size_t)BATCH * SEQ * DIM];
__device__ __half g_wh [(size_t)BATCH * SEQ * DADIM];  // tanh output
__device__ __half g_ah [(size_t)BATCH * NLDIM * SEQ];  // logits -> softmax (fp16)
__device__ __half g_w1h[DADIM * DIM];
__device__ __half g_w2h[NLDIM * DADIM];

// ---------------- PTX helpers (family-portable: no tcgen05) ----------
__device__ __forceinline__ uint32_t smem_u32(const void* p) {
    uint32_t a;
    asm("{ .reg .u64 t; cvta.to.shared.u64 t, %1; cvt.u32.u64 %0, t; }" : "=r"(a) : "l"(p));
    return a;
}
__device__ __forceinline__ void cp16(uint32_t saddr, const void* g) {
    asm volatile("cp.async.cg.shared.global [%0], [%1], 16;" :: "r"(saddr), "l"(g));
}
__device__ __forceinline__ void cp_commit() { asm volatile("cp.async.commit_group;"); }
__device__ __forceinline__ void cp_wait0()  { asm volatile("cp.async.wait_group 0;"); }
__device__ __forceinline__ void cp_wait2()  { asm volatile("cp.async.wait_group 2;"); }

__device__ __forceinline__ float tanh_ap(float x) {
    float r;
    asm("tanh.approx.f32 %0, %1;" : "=f"(r) : "f"(x));
    return r;
}

__device__ __forceinline__ void ldsm_x4(uint32_t& r0, uint32_t& r1, uint32_t& r2, uint32_t& r3,
                                        uint32_t addr) {
    asm volatile("ldmatrix.sync.aligned.m8n8.x4.shared.b16 {%0,%1,%2,%3}, [%4];"
                 : "=r"(r0), "=r"(r1), "=r"(r2), "=r"(r3) : "r"(addr));
}
__device__ __forceinline__ void ldsm_x4_t(uint32_t& r0, uint32_t& r1, uint32_t& r2, uint32_t& r3,
                                          uint32_t addr) {
    asm volatile("ldmatrix.sync.aligned.m8n8.x4.trans.shared.b16 {%0,%1,%2,%3}, [%4];"
                 : "=r"(r0), "=r"(r1), "=r"(r2), "=r"(r3) : "r"(addr));
}
__device__ __forceinline__ void mma16816(float& c0, float& c1, float& c2, float& c3,
                                         uint32_t a0, uint32_t a1, uint32_t a2, uint32_t a3,
                                         uint32_t b0, uint32_t b1) {
    asm volatile(
        "mma.sync.aligned.m16n8k16.row.col.f32.f16.f16.f32 "
        "{%0,%1,%2,%3}, {%4,%5,%6,%7}, {%8,%9}, {%0,%1,%2,%3};"
        : "+f"(c0), "+f"(c1), "+f"(c2), "+f"(c3)
        : "r"(a0), "r"(a1), "r"(a2), "r"(a3), "r"(b0), "r"(b1));
}

// tile geometry: CTA 128x128, BK=32, 256 thr, 8 warps (4M x 2N), warp 32x64,
// 4-stage ring (R5/R10-proven config, R5 loaders verbatim)
#define ROWB   80                 // A/B-NT smem row bytes (32 fp16 = 64 B + 16 pad)
#define ATILE  (128 * ROWB)       // 10240
#define BROWB  272                // NN B smem row bytes (128 fp16 = 256 B + 16 pad)
#define BTILE_NN (32 * BROWB)     // 8704
#define STG_NT (ATILE + ATILE)    // 20480
#define STG_NN (ATILE + BTILE_NN) // 18944
#define SMEM_NT (4 * STG_NT)      // 81920
#define SMEM_NN (4 * STG_NN)      // 75776

// ===========================================================================
// NT fp16 GEMM: C[m,n] = sum_k A[m,k]*B[n,k]
// mode 0: fp32 C.  mode 1: tanh.approx(acc) -> fp16 Ch.  mode 2: acc -> fp16 Ch.
// Inner loop: B fragments for both k-halves front-loaded (double-buffered in
// regs); A fragments reloaded per k-half. Fits 128-reg / 2-CTA budget.
// ===========================================================================
__global__ __launch_bounds__(256, 2) void gemm_f16_nt(
    const __half* __restrict__ A, long long sA,
    const __half* __restrict__ B, long long sB,
    float* __restrict__ C, __half* __restrict__ Ch,
    long long sC, int N, int K, int mode)
{
    extern __shared__ __align__(128) char smem[];
    const uint32_t s0 = smem_u32(smem);

    const int t = threadIdx.x;
    const int bz = blockIdx.z;
    const int m0 = blockIdx.y * 128;
    const int n0 = blockIdx.x * 128;

    const int lane = t & 31;
    const int wid  = t >> 5;
    const int wm   = wid & 3;
    const int wn   = wid >> 2;
    const int g    = lane >> 3;
    const int lr   = lane & 7;

    const uint32_t abase = (uint32_t)((wm * 32 + ((g & 1) << 3) + lr) * ROWB + ((g >> 1) << 4));
    const uint32_t bbase = (uint32_t)((wn * 64 + ((g >> 1) << 3) + lr) * ROWB + ((g & 1) << 4));

    // R5 loader: lanes 0-3 fetch 64 contiguous bytes of one row (full sectors)
    const int r0_ = t >> 2, s0_ = (t & 3);

    const __half* Ab = A + (size_t)bz * sA + (size_t)m0 * K;
    const __half* Bb = B + (size_t)bz * sB + (size_t)n0 * K;

    const int nch = K >> 5;

    float acc[2][8][4];
    #pragma unroll
    for (int i = 0; i < 2; i++)
        #pragma unroll
        for (int j = 0; j < 8; j++)
            #pragma unroll
            for (int q = 0; q < 4; q++) acc[i][j][q] = 0.f;

    auto load_chunk = [&](int c) {
        const int kk = c << 5;
        const uint32_t sa = s0 + (uint32_t)((c & 3) * STG_NT);
        const uint32_t sb = sa + ATILE;
        #pragma unroll
        for (int i = 0; i < 2; i++) {
            const int row = r0_ + i * 64;
            cp16(sa + (uint32_t)(row * ROWB + s0_ * 16), Ab + (size_t)row * K + kk + s0_ * 8);
        }
        #pragma unroll
        for (int i = 0; i < 2; i++) {
            const int row = r0_ + i * 64;
            cp16(sb + (uint32_t)(row * ROWB + s0_ * 16), Bb + (size_t)row * K + kk + s0_ * 8);
        }
        cp_commit();
    };

    load_chunk(0);
    load_chunk(1);
    load_chunk(2);

    for (int c = 0; c < nch; c++) {
        if (c + 2 < nch) cp_wait2(); else cp_wait0();
        __syncthreads();
        if (c + 3 < nch) load_chunk(c + 3);

        const uint32_t base = s0 + (uint32_t)((c & 3) * STG_NT);
        const uint32_t sa = base + abase;
        const uint32_t sb = base + ATILE + bbase;

        // front-load B fragments for both k-halves
        uint32_t b[2][4][4];
        #pragma unroll
        for (int ks = 0; ks < 2; ks++)
            #pragma unroll
            for (int p = 0; p < 4; p++)
                ldsm_x4(b[ks][p][0], b[ks][p][1], b[ks][p][2], b[ks][p][3],
                        sb + (uint32_t)(p * 16 * ROWB + ks * 32));

        #pragma unroll
        for (int ks = 0; ks < 2; ks++) {
            uint32_t a[2][4];
            #pragma unroll
            for (int mi = 0; mi < 2; mi++)
                ldsm_x4(a[mi][0], a[mi][1], a[mi][2], a[mi][3],
                        sa + (uint32_t)(mi * 16 * ROWB + ks * 32));
            #pragma unroll
            for (int mi = 0; mi < 2; mi++)
                #pragma unroll
                for (int j = 0; j < 8; j++) {
                    const int p = j >> 1, h = j & 1;
                    mma16816(acc[mi][j][0], acc[mi][j][1], acc[mi][j][2], acc[mi][j][3],
                             a[mi][0], a[mi][1], a[mi][2], a[mi][3],
                             b[ks][p][h * 2], b[ks][p][h * 2 + 1]);
                }
        }
    }

    const int rrow = lane >> 2;
    const int rcol = (lane & 3) * 2;
    #pragma unroll
    for (int mi = 0; mi < 2; mi++) {
        const int gr = m0 + wm * 32 + mi * 16 + rrow;
        #pragma unroll
        for (int j = 0; j < 8; j++) {
            const int gc = n0 + wn * 64 + j * 8 + rcol;
            const size_t o0 = (size_t)bz * sC + (size_t)gr * N + gc;
            const size_t o1 = o0 + (size_t)8 * N;
            if (mode == 0) {
                *(float2*)(C + o0) = make_float2(acc[mi][j][0], acc[mi][j][1]);
                *(float2*)(C + o1) = make_float2(acc[mi][j][2], acc[mi][j][3]);
            } else if (mode == 1) {
                union { __half h[2]; uint32_t u; } P0, P1;
                P0.h[0] = __float2half_rn(tanh_ap(acc[mi][j][0]));
                P0.h[1] = __float2half_rn(tanh_ap(acc[mi][j][1]));
                P1.h[0] = __float2half_rn(tanh_ap(acc[mi][j][2]));
                P1.h[1] = __float2half_rn(tanh_ap(acc[mi][j][3]));
                *(uint32_t*)(Ch + o0) = P0.u;
                *(uint32_t*)(Ch + o1) = P1.u;
            } else {
                union { __half h[2]; uint32_t u; } P0, P1;
                P0.h[0] = __float2half_rn(acc[mi][j][0]);
                P0.h[1] = __float2half_rn(acc[mi][j][1]);
                P1.h[0] = __float2half_rn(acc[mi][j][2]);
                P1.h[1] = __float2half_rn(acc[mi][j][3]);
                *(uint32_t*)(Ch + o0) = P0.u;
                *(uint32_t*)(Ch + o1) = P1.u;
            }
        }
    }
}

// ===========================================================================
// NN fp16 GEMM: C[m,n] = sum_k A[m,k]*B[k,n]; B row-major [K, NB] via
// ldmatrix.trans. fp32 output. Same B-fragment front-loading.
// ===========================================================================
__global__ __launch_bounds__(256, 2) void gemm_f16_nn(
    const __half* __restrict__ A, long long sA,
    const __half* __restrict__ B, long long sB,
    float* __restrict__ C, long long sC, int N, int NB, int K)
{
    extern __shared__ __align__(128) char smem[];
    const uint32_t s0 = smem_u32(smem);

    const int t = threadIdx.x;
    const int bz = blockIdx.z;
    const int m0 = blockIdx.y * 128;
    const int n0 = blockIdx.x * 128;

    const int lane = t & 31;
    const int wid  = t >> 5;
    const int wm   = wid & 3;
    const int wn   = wid >> 2;
    const int g    = lane >> 3;
    const int lr   = lane & 7;

    const uint32_t abase = (uint32_t)((wm * 32 + ((g & 1) << 3) + lr) * ROWB + ((g >> 1) << 4));
    const uint32_t bbase = (uint32_t)(((g & 1) * 8 + lr) * BROWB + (wn * 64 + (g >> 1) * 8) * 2);

    const int ar_ = t >> 2, ac_ = (t & 3);   // A loader (R5)
    const int br_ = t >> 4, bc_ = (t & 15);  // B loader (R5)

    const __half* Ab = A + (size_t)bz * sA + (size_t)m0 * K;
    const __half* Bb = B + (size_t)bz * sB + n0;

    const int nch = K >> 5;

    float acc[2][8][4];
    #pragma unroll
    for (int i = 0; i < 2; i++)
        #pragma unroll
        for (int j = 0; j < 8; j++)
            #pragma unroll
            for (int q = 0; q < 4; q++) acc[i][j][q] = 0.f;

    auto load_chunk = [&](int c) {
        const int kk = c << 5;
        const uint32_t sa = s0 + (uint32_t)((c & 3) * STG_NN);
        const uint32_t sb = sa + ATILE;
        #pragma unroll
        for (int i = 0; i < 2; i++) {
            const int row = ar_ + i * 64;
            cp16(sa + (uint32_t)(row * ROWB + ac_ * 16), Ab + (size_t)row * K + kk + ac_ * 8);
        }
        #pragma unroll
        for (int i = 0; i < 2; i++) {
            const int row = br_ + i * 16;
            cp16(sb + (uint32_t)(row * BROWB + bc_ * 16),
                 Bb + (size_t)(kk + row) * NB + bc_ * 8);
        }
        cp_commit();
    };

    load_chunk(0);
    load_chunk(1);
    load_chunk(2);

    for (int c = 0; c < nch; c++) {
        if (c + 2 < nch) cp_wait2(); else cp_wait0();
        __syncthreads();
        if (c + 3 < nch) load_chunk(c + 3);

        const uint32_t base = s0 + (uint32_t)((c & 3) * STG_NN);
        const uint32_t sa = base + abase;
        const uint32_t sb = base + ATILE + bbase;

        // front-load B fragments for both k-halves
        uint32_t b[2][4][4];
        #pragma unroll
        for (int ks = 0; ks < 2; ks++)
            #pragma unroll
            for (int p = 0; p < 4; p++)
                ldsm_x4_t(b[ks][p][0], b[ks][p][1], b[ks][p][2], b[ks][p][3],
                          sb + (uint32_t)(ks * 16 * BROWB + p * 32));

        #pragma unroll
        for (int ks = 0; ks < 2; ks++) {
            uint32_t a[2][4];
            #pragma unroll
            for (int mi = 0; mi < 2; mi++)
                ldsm_x4(a[mi][0], a[mi][1], a[mi][2], a[mi][3],
                        sa + (uint32_t)(mi * 16 * ROWB + ks * 32));
            #pragma unroll
            for (int mi = 0; mi < 2; mi++)
                #pragma unroll
                for (int j = 0; j < 8; j++) {
                    const int p = j >> 1, h = j & 1;
                    mma16816(acc[mi][j][0], acc[mi][j][1], acc[mi][j][2], acc[mi][j][3],
                             a[mi][0], a[mi][1], a[mi][2], a[mi][3],
                             b[ks][p][h * 2], b[ks][p][h * 2 + 1]);
                }
        }
    }

    const int rrow = lane >> 2;
    const int rcol = (lane & 3) * 2;
    #pragma unroll
    for (int mi = 0; mi < 2; mi++) {
        const int gr = m0 + wm * 32 + mi * 16 + rrow;
        #pragma unroll
        for (int j = 0; j < 8; j++) {
            const int gc = n0 + wn * 64 + j * 8 + rcol;
            const size_t o0 = (size_t)bz * sC + (size_t)gr * N + gc;
            const size_t o1 = o0 + (size_t)8 * N;
            *(float2*)(C + o0) = make_float2(acc[mi][j][0], acc[mi][j][1]);
            *(float2*)(C + o1) = make_float2(acc[mi][j][2], acc[mi][j][3]);
        }
    }
}

// ---------------------------------------------------------------------------
// elementwise fp32 -> fp16: x (blocks [0, NX)), then W1, then W2 in one grid.
// ---------------------------------------------------------------------------
#define NXBLK ((BATCH * SEQ * DIM) / 1024)
#define NW1BLK ((DADIM * DIM) / 1024)
#define NW2BLK ((NLDIM * DADIM) / 1024)
__global__ __launch_bounds__(256) void cvt_all(
    const float* __restrict__ x, __half* __restrict__ xh,
    const float* __restrict__ W1, __half* __restrict__ w1h,
    const float* __restrict__ W2, __half* __restrict__ w2h)
{
    const float* s; __half* h; size_t i;
    int blk = blockIdx.x;
    if (blk < NXBLK)               { s = x;  h = xh;  i = (size_t)blk; }
    else if (blk < NXBLK + NW1BLK) { s = W1; h = w1h; i = (size_t)(blk - NXBLK); }
    else                           { s = W2; h = w2h; i = (size_t)(blk - NXBLK - NW1BLK); }
    i = (i * 256 + threadIdx.x) * 4;
    float4 v = *(const float4*)(s + i);
    union { __half h[4]; uint2 u; } H;
    H.h[0] = __float2half_rn(v.x);
    H.h[1] = __float2half_rn(v.y);
    H.h[2] = __float2half_rn(v.z);
    H.h[3] = __float2half_rn(v.w);
    *(uint2*)(h + i) = H.u;
}

// ---------------------------------------------------------------------------
// softmax over 2048-row of fp16 logits (in place) + fp32 att to output.
// ---------------------------------------------------------------------------
__global__ __launch_bounds__(256) void softmax_h(
    __half* __restrict__ lg, float* __restrict__ att)
{
    const size_t base = (size_t)blockIdx.x * SEQ;
    __half* p = lg + base;
    float* ao = att + base;
    const int t = threadIdx.x;
    const int w = t >> 5, lane = t & 31;

    union { __half h[8]; uint4 u; } V;
    V.u = *(const uint4*)(p + t * 8);
    float v[8];
    float m = -1e30f;
    #pragma unroll
    for (int k = 0; k < 8; k++) { v[k] = __half2float(V.h[k]); m = fmaxf(m, v[k]); }
    #pragma unroll
    for (int o = 16; o; o >>= 1) m = fmaxf(m, __shfl_xor_sync(0xffffffffu, m, o));

    __shared__ float sm[8], ss[8];
    if (lane == 0) sm[w] = m;
    __syncthreads();
    float bm = sm[0];
    #pragma unroll
    for (int i = 1; i < 8; i++) bm = fmaxf(bm, sm[i]);

    float s = 0.f;
    #pragma unroll
    for (int k = 0; k < 8; k++) { v[k] = __expf(v[k] - bm); s += v[k]; }
    #pragma unroll
    for (int o = 16; o; o >>= 1) s += __shfl_xor_sync(0xffffffffu, s, o);
    if (lane == 0) ss[w] = s;
    __syncthreads();
    float bs = 0.f;
    #pragma unroll
    for (int i = 0; i < 8; i++) bs += ss[i];
    const float inv = 1.0f / bs;

    union { __half h[8]; uint4 u; } O;
    #pragma unroll
    for (int k = 0; k < 8; k += 4) {
        float r0 = v[k] * inv, r1 = v[k+1] * inv, r2 = v[k+2] * inv, r3 = v[k+3] * inv;
        *(float4*)(ao + t * 8 + k) = make_float4(r0, r1, r2, r3);
        O.h[k]   = __float2half_rn(r0);
        O.h[k+1] = __float2half_rn(r1);
        O.h[k+2] = __float2half_rn(r2);
        O.h[k+3] = __float2half_rn(r3);
    }
    *(uint4*)(p + t * 8) = O.u;
}

// ---------------------------------------------------------------------------
// weighted_output[r] = dot(ctx[r,:], W3[r % NL,:]) + b3[r % NL]  (all fp32)
// ---------------------------------------------------------------------------
__global__ __launch_bounds__(256) void weighted_out(
    const float* __restrict__ ctx, const float* __restrict__ W3,
    const float* __restrict__ b3, float* __restrict__ out)
{
    const int r = blockIdx.x * 8 + (threadIdx.x >> 5);
    const int lane = threadIdx.x & 31;
    const int n = r & (NLDIM - 1);
    const float* c = ctx + (size_t)r * DIM;
    const float* w = W3 + (size_t)n * DIM;
    float s = 0.f;
    #pragma unroll
    for (int j = 0; j < 4; j++) {
        float4 cv = *(const float4*)(c + lane * 4 + j * 128);
        float4 wv = *(const float4*)(w + lane * 4 + j * 128);
        s += cv.x * wv.x + cv.y * wv.y + cv.z * wv.z + cv.w * wv.w;
    }
    #pragma unroll
    for (int o = 16; o; o >>= 1) s += __shfl_xor_sync(0xffffffffu, s, o);
    if (lane == 0) out[r] = s + b3[n];
}

// ---------------------------------------------------------------------------
extern "C" void kernel_launch(void* const* d_in, const int* in_sizes, int n_in,
                              void* d_out, int out_size)
{
    const float* x  = (const float*)d_in[0];
    const float* W1 = (const float*)d_in[1];
    const float* W2 = (const float*)d_in[2];
    const float* W3 = (const float*)d_in[3];
    const float* b3 = (const float*)d_in[4];

    float* ctx = (float*)d_out;                       // [B, NL, D]
    float* wo  = ctx + (size_t)BATCH * NLDIM * DIM;   // [B, NL]
    float* att = wo + (size_t)BATCH * NLDIM;          // [B, NL, L]

    __half *xh, *wh, *ah, *w1h, *w2h;
    cudaGetSymbolAddress((void**)&xh, g_xh);
    cudaGetSymbolAddress((void**)&wh, g_wh);
    cudaGetSymbolAddress((void**)&ah, g_ah);
    cudaGetSymbolAddress((void**)&w1h, g_w1h);
    cudaGetSymbolAddress((void**)&w2h, g_w2h);

    cudaFuncSetAttribute(gemm_f16_nt, cudaFuncAttributeMaxDynamicSharedMemorySize, SMEM_NT);
    cudaFuncSetAttribute(gemm_f16_nn, cudaFuncAttributeMaxDynamicSharedMemorySize, SMEM_NN);

    // fp32 -> fp16 conversions (single launch)
    cvt_all<<<NXBLK + NW1BLK + NW2BLK, 256>>>(x, xh, W1, w1h, W2, w2h);

    // GEMM1 (NT): w = tanh(x @ W1^T) -> fp16 (tanh.approx epilogue)
    {
        dim3 g(DADIM / 128, (BATCH * SEQ) / 128, 1);
        gemm_f16_nt<<<g, 256, SMEM_NT>>>(xh, 0, w1h, 0,
                                         nullptr, wh, 0, DADIM, DIM, 1);
    }
    // GEMM2 (NT): logits[b,n,l] = W2 @ w[b]^T -> fp16 (mode 2)
    {
        dim3 g(SEQ / 128, NLDIM / 128, BATCH);
        gemm_f16_nt<<<g, 256, SMEM_NT>>>(w2h, 0,
                                         wh, (long long)SEQ * DADIM,
                                         nullptr, ah,
                                         (long long)NLDIM * SEQ, SEQ, DADIM, 2);
    }
    // softmax over L: fp16 logits in place -> normalized fp16 + fp32 att output
    softmax_h<<<BATCH * NLDIM, 256>>>(ah, att);

    // GEMM3 (NN): ctx[b,n,d] = att[b] @ x[b]; B = x row-major [L, D]
    {
        dim3 g(DIM / 128, NLDIM / 128, BATCH);
        gemm_f16_nn<<<g, 256, SMEM_NN>>>(ah, (long long)NLDIM * SEQ,
                                         xh, (long long)SEQ * DIM,
                                         ctx, (long long)NLDIM * DIM,
                                         DIM, DIM, SEQ);
    }
    // weighted output
    weighted_out<<<(BATCH * NLDIM) / 8, 256>>>(ctx, W3, b3, wo);
}

// round 13
// speedup vs baseline: 1.0184x; 1.0184x over previous
#include <cuda_runtime.h>
#include <cuda_fp16.h>
#include <math.h>
#include <stdint.h>

#define BATCH 32
#define SEQ   2048
#define DIM   512
#define DADIM 512
#define NLDIM 512

// ---------------- fp16 scratch (static, allocation-free) ----------------
__device__ __half g_xh [(size_t)BATCH * SEQ * DIM];
__device__ __half g_wh [(size_t)BATCH * SEQ * DADIM];  // tanh output
__device__ __half g_ah [(size_t)BATCH * NLDIM * SEQ];  // logits -> softmax (fp16)
__device__ __half g_w1h[DADIM * DIM];
__device__ __half g_w2h[NLDIM * DADIM];

// ---------------- PTX helpers (family-portable: no tcgen05) ----------
__device__ __forceinline__ uint32_t smem_u32(const void* p) {
    uint32_t a;
    asm("{ .reg .u64 t; cvta.to.shared.u64 t, %1; cvt.u32.u64 %0, t; }" : "=r"(a) : "l"(p));
    return a;
}
__device__ __forceinline__ void cp16(uint32_t saddr, const void* g) {
    asm volatile("cp.async.cg.shared.global [%0], [%1], 16;" :: "r"(saddr), "l"(g));
}
__device__ __forceinline__ void cp_commit() { asm volatile("cp.async.commit_group;"); }
__device__ __forceinline__ void cp_wait0()  { asm volatile("cp.async.wait_group 0;"); }
__device__ __forceinline__ void cp_wait2()  { asm volatile("cp.async.wait_group 2;"); }

__device__ __forceinline__ float tanh_ap(float x) {
    float r;
    asm("tanh.approx.f32 %0, %1;" : "=f"(r) : "f"(x));
    return r;
}

__device__ __forceinline__ void ldsm_x4(uint32_t& r0, uint32_t& r1, uint32_t& r2, uint32_t& r3,
                                        uint32_t addr) {
    asm volatile("ldmatrix.sync.aligned.m8n8.x4.shared.b16 {%0,%1,%2,%3}, [%4];"
                 : "=r"(r0), "=r"(r1), "=r"(r2), "=r"(r3) : "r"(addr));
}
__device__ __forceinline__ void ldsm_x4_t(uint32_t& r0, uint32_t& r1, uint32_t& r2, uint32_t& r3,
                                          uint32_t addr) {
    asm volatile("ldmatrix.sync.aligned.m8n8.x4.trans.shared.b16 {%0,%1,%2,%3}, [%4];"
                 : "=r"(r0), "=r"(r1), "=r"(r2), "=r"(r3) : "r"(addr));
}
__device__ __forceinline__ void mma16816(float& c0, float& c1, float& c2, float& c3,
                                         uint32_t a0, uint32_t a1, uint32_t a2, uint32_t a3,
                                         uint32_t b0, uint32_t b1) {
    asm volatile(
        "mma.sync.aligned.m16n8k16.row.col.f32.f16.f16.f32 "
        "{%0,%1,%2,%3}, {%4,%5,%6,%7}, {%8,%9}, {%0,%1,%2,%3};"
        : "+f"(c0), "+f"(c1), "+f"(c2), "+f"(c3)
        : "r"(a0), "r"(a1), "r"(a2), "r"(a3), "r"(b0), "r"(b1));
}

// tile geometry: CTA 128x128, BK=32, 256 thr, 8 warps (4M x 2N), warp 32x64,
// 4-stage ring (R5/R10-proven config, R10 mainloop byte-exact)
#define ROWB   80                 // A/B-NT smem row bytes (32 fp16 = 64 B + 16 pad)
#define ATILE  (128 * ROWB)       // 10240
#define BROWB  272                // NN B smem row bytes (128 fp16 = 256 B + 16 pad)
#define BTILE_NN (32 * BROWB)     // 8704
#define STG_NT (ATILE + ATILE)    // 20480
#define STG_NN (ATILE + BTILE_NN) // 18944
#define SMEM_NT (4 * STG_NT)      // 81920
#define SMEM_NN (4 * STG_NN)      // 75776

// ===========================================================================
// NT fp16 GEMM: C[m,n] = sum_k A[m,k]*B[n,k]
// mode 0: fp32 C.  mode 1: tanh.approx(acc) -> fp16 Ch.  mode 2: acc -> fp16 Ch.
// ===========================================================================
__global__ __launch_bounds__(256, 2) void gemm_f16_nt(
    const __half* __restrict__ A, long long sA,
    const __half* __restrict__ B, long long sB,
    float* __restrict__ C, __half* __restrict__ Ch,
    long long sC, int N, int K, int mode)
{
    extern __shared__ __align__(128) char smem[];
    const uint32_t s0 = smem_u32(smem);

    const int t = threadIdx.x;
    const int bz = blockIdx.z;
    const int m0 = blockIdx.y * 128;
    const int n0 = blockIdx.x * 128;

    const int lane = t & 31;
    const int wid  = t >> 5;
    const int wm   = wid & 3;
    const int wn   = wid >> 2;
    const int g    = lane >> 3;
    const int lr   = lane & 7;

    const uint32_t abase = (uint32_t)((wm * 32 + ((g & 1) << 3) + lr) * ROWB + ((g >> 1) << 4));
    const uint32_t bbase = (uint32_t)((wn * 64 + ((g >> 1) << 3) + lr) * ROWB + ((g & 1) << 4));

    // R5 loader: lanes 0-3 fetch 64 contiguous bytes of one row (full sectors)
    const int r0_ = t >> 2, s0_ = (t & 3);

    const __half* Ab = A + (size_t)bz * sA + (size_t)m0 * K;
    const __half* Bb = B + (size_t)bz * sB + (size_t)n0 * K;

    const int nch = K >> 5;

    float acc[2][8][4];
    #pragma unroll
    for (int i = 0; i < 2; i++)
        #pragma unroll
        for (int j = 0; j < 8; j++)
            #pragma unroll
            for (int q = 0; q < 4; q++) acc[i][j][q] = 0.f;

    auto load_chunk = [&](int c) {
        const int kk = c << 5;
        const uint32_t sa = s0 + (uint32_t)((c & 3) * STG_NT);
        const uint32_t sb = sa + ATILE;
        #pragma unroll
        for (int i = 0; i < 2; i++) {
            const int row = r0_ + i * 64;
            cp16(sa + (uint32_t)(row * ROWB + s0_ * 16), Ab + (size_t)row * K + kk + s0_ * 8);
        }
        #pragma unroll
        for (int i = 0; i < 2; i++) {
            const int row = r0_ + i * 64;
            cp16(sb + (uint32_t)(row * ROWB + s0_ * 16), Bb + (size_t)row * K + kk + s0_ * 8);
        }
        cp_commit();
    };

    load_chunk(0);
    load_chunk(1);
    load_chunk(2);

    for (int c = 0; c < nch; c++) {
        if (c + 2 < nch) cp_wait2(); else cp_wait0();
        __syncthreads();
        if (c + 3 < nch) load_chunk(c + 3);

        const uint32_t base = s0 + (uint32_t)((c & 3) * STG_NT);
        const uint32_t sa = base + abase;
        const uint32_t sb = base + ATILE + bbase;

        #pragma unroll
        for (int ks = 0; ks < 2; ks++) {
            uint32_t a[2][4];
            uint32_t b[4][4];
            #pragma unroll
            for (int mi = 0; mi < 2; mi++)
                ldsm_x4(a[mi][0], a[mi][1], a[mi][2], a[mi][3],
                        sa + (uint32_t)(mi * 16 * ROWB + ks * 32));
            #pragma unroll
            for (int p = 0; p < 4; p++)
                ldsm_x4(b[p][0], b[p][1], b[p][2], b[p][3],
                        sb + (uint32_t)(p * 16 * ROWB + ks * 32));
            #pragma unroll
            for (int mi = 0; mi < 2; mi++)
                #pragma unroll
                for (int j = 0; j < 8; j++) {
                    const int p = j >> 1, h = j & 1;
                    mma16816(acc[mi][j][0], acc[mi][j][1], acc[mi][j][2], acc[mi][j][3],
                             a[mi][0], a[mi][1], a[mi][2], a[mi][3],
                             b[p][h * 2], b[p][h * 2 + 1]);
                }
        }
    }

    const int rrow = lane >> 2;
    const int rcol = (lane & 3) * 2;
    #pragma unroll
    for (int mi = 0; mi < 2; mi++) {
        const int gr = m0 + wm * 32 + mi * 16 + rrow;
        #pragma unroll
        for (int j = 0; j < 8; j++) {
            const int gc = n0 + wn * 64 + j * 8 + rcol;
            const size_t o0 = (size_t)bz * sC + (size_t)gr * N + gc;
            const size_t o1 = o0 + (size_t)8 * N;
            if (mode == 0) {
                *(float2*)(C + o0) = make_float2(acc[mi][j][0], acc[mi][j][1]);
                *(float2*)(C + o1) = make_float2(acc[mi][j][2], acc[mi][j][3]);
            } else if (mode == 1) {
                union { __half h[2]; uint32_t u; } P0, P1;
                P0.h[0] = __float2half_rn(tanh_ap(acc[mi][j][0]));
                P0.h[1] = __float2half_rn(tanh_ap(acc[mi][j][1]));
                P1.h[0] = __float2half_rn(tanh_ap(acc[mi][j][2]));
                P1.h[1] = __float2half_rn(tanh_ap(acc[mi][j][3]));
                *(uint32_t*)(Ch + o0) = P0.u;
                *(uint32_t*)(Ch + o1) = P1.u;
            } else {
                union { __half h[2]; uint32_t u; } P0, P1;
                P0.h[0] = __float2half_rn(acc[mi][j][0]);
                P0.h[1] = __float2half_rn(acc[mi][j][1]);
                P1.h[0] = __float2half_rn(acc[mi][j][2]);
                P1.h[1] = __float2half_rn(acc[mi][j][3]);
                *(uint32_t*)(Ch + o0) = P0.u;
                *(uint32_t*)(Ch + o1) = P1.u;
            }
        }
    }
}

// ===========================================================================
// NN fp16 GEMM: C[m,n] = sum_k A[m,k]*B[k,n]; B row-major [K, NB] via
// ldmatrix.trans. fp32 output. (R10 mainloop byte-exact)
// ===========================================================================
__global__ __launch_bounds__(256, 2) void gemm_f16_nn(
    const __half* __restrict__ A, long long sA,
    const __half* __restrict__ B, long long sB,
    float* __restrict__ C, long long sC, int N, int NB, int K)
{
    extern __shared__ __align__(128) char smem[];
    const uint32_t s0 = smem_u32(smem);

    const int t = threadIdx.x;
    const int bz = blockIdx.z;
    const int m0 = blockIdx.y * 128;
    const int n0 = blockIdx.x * 128;

    const int lane = t & 31;
    const int wid  = t >> 5;
    const int wm   = wid & 3;
    const int wn   = wid >> 2;
    const int g    = lane >> 3;
    const int lr   = lane & 7;

    const uint32_t abase = (uint32_t)((wm * 32 + ((g & 1) << 3) + lr) * ROWB + ((g >> 1) << 4));
    const uint32_t bbase = (uint32_t)(((g & 1) * 8 + lr) * BROWB + (wn * 64 + (g >> 1) * 8) * 2);

    const int ar_ = t >> 2, ac_ = (t & 3);   // A loader (R5)
    const int br_ = t >> 4, bc_ = (t & 15);  // B loader (R5)

    const __half* Ab = A + (size_t)bz * sA + (size_t)m0 * K;
    const __half* Bb = B + (size_t)bz * sB + n0;

    const int nch = K >> 5;

    float acc[2][8][4];
    #pragma unroll
    for (int i = 0; i < 2; i++)
        #pragma unroll
        for (int j = 0; j < 8; j++)
            #pragma unroll
            for (int q = 0; q < 4; q++) acc[i][j][q] = 0.f;

    auto load_chunk = [&](int c) {
        const int kk = c << 5;
        const uint32_t sa = s0 + (uint32_t)((c & 3) * STG_NN);
        const uint32_t sb = sa + ATILE;
        #pragma unroll
        for (int i = 0; i < 2; i++) {
            const int row = ar_ + i * 64;
            cp16(sa + (uint32_t)(row * ROWB + ac_ * 16), Ab + (size_t)row * K + kk + ac_ * 8);
        }
        #pragma unroll
        for (int i = 0; i < 2; i++) {
            const int row = br_ + i * 16;
            cp16(sb + (uint32_t)(row * BROWB + bc_ * 16),
                 Bb + (size_t)(kk + row) * NB + bc_ * 8);
        }
        cp_commit();
    };

    load_chunk(0);
    load_chunk(1);
    load_chunk(2);

    for (int c = 0; c < nch; c++) {
        if (c + 2 < nch) cp_wait2(); else cp_wait0();
        __syncthreads();
        if (c + 3 < nch) load_chunk(c + 3);

        const uint32_t base = s0 + (uint32_t)((c & 3) * STG_NN);
        const uint32_t sa = base + abase;
        const uint32_t sb = base + ATILE + bbase;

        #pragma unroll
        for (int ks = 0; ks < 2; ks++) {
            uint32_t a[2][4];
            uint32_t b[4][4];
            #pragma unroll
            for (int mi = 0; mi < 2; mi++)
                ldsm_x4(a[mi][0], a[mi][1], a[mi][2], a[mi][3],
                        sa + (uint32_t)(mi * 16 * ROWB + ks * 32));
            #pragma unroll
            for (int p = 0; p < 4; p++)
                ldsm_x4_t(b[p][0], b[p][1], b[p][2], b[p][3],
                          sb + (uint32_t)(ks * 16 * BROWB + p * 32));
            #pragma unroll
            for (int mi = 0; mi < 2; mi++)
                #pragma unroll
                for (int j = 0; j < 8; j++) {
                    const int p = j >> 1, h = j & 1;
                    mma16816(acc[mi][j][0], acc[mi][j][1], acc[mi][j][2], acc[mi][j][3],
                             a[mi][0], a[mi][1], a[mi][2], a[mi][3],
                             b[p][h * 2], b[p][h * 2 + 1]);
                }
        }
    }

    const int rrow = lane >> 2;
    const int rcol = (lane & 3) * 2;
    #pragma unroll
    for (int mi = 0; mi < 2; mi++) {
        const int gr = m0 + wm * 32 + mi * 16 + rrow;
        #pragma unroll
        for (int j = 0; j < 8; j++) {
            const int gc = n0 + wn * 64 + j * 8 + rcol;
            const size_t o0 = (size_t)bz * sC + (size_t)gr * N + gc;
            const size_t o1 = o0 + (size_t)8 * N;
            *(float2*)(C + o0) = make_float2(acc[mi][j][0], acc[mi][j][1]);
            *(float2*)(C + o1) = make_float2(acc[mi][j][2], acc[mi][j][3]);
        }
    }
}

// ---------------------------------------------------------------------------
// elementwise fp32 -> fp16: x, W1, W2 in a single grid.
// ---------------------------------------------------------------------------
#define NXBLK  ((BATCH * SEQ * DIM) / 1024)
#define NW1BLK ((DADIM * DIM) / 1024)
#define NW2BLK ((NLDIM * DADIM) / 1024)
__global__ __launch_bounds__(256) void cvt_all(
    const float* __restrict__ x, __half* __restrict__ xh,
    const float* __restrict__ W1, __half* __restrict__ w1h,
    const float* __restrict__ W2, __half* __restrict__ w2h)
{
    const float* s; __half* h; size_t i;
    int blk = blockIdx.x;
    if (blk < NXBLK)               { s = x;  h = xh;  i = (size_t)blk; }
    else if (blk < NXBLK + NW1BLK) { s = W1; h = w1h; i = (size_t)(blk - NXBLK); }
    else                           { s = W2; h = w2h; i = (size_t)(blk - NXBLK - NW1BLK); }
    i = (i * 256 + threadIdx.x) * 4;
    float4 v = *(const float4*)(s + i);
    union { __half h[4]; uint2 u; } H;
    H.h[0] = __float2half_rn(v.x);
    H.h[1] = __float2half_rn(v.y);
    H.h[2] = __float2half_rn(v.z);
    H.h[3] = __float2half_rn(v.w);
    *(uint2*)(h + i) = H.u;
}

// ---------------------------------------------------------------------------
// softmax over 2048-row of fp16 logits (in place) + fp32 att to output.
// ---------------------------------------------------------------------------
__global__ __launch_bounds__(256) void softmax_h(
    __half* __restrict__ lg, float* __restrict__ att)
{
    const size_t base = (size_t)blockIdx.x * SEQ;
    __half* p = lg + base;
    float* ao = att + base;
    const int t = threadIdx.x;
    const int w = t >> 5, lane = t & 31;

    union { __half h[8]; uint4 u; } V;
    V.u = *(const uint4*)(p + t * 8);
    float v[8];
    float m = -1e30f;
    #pragma unroll
    for (int k = 0; k < 8; k++) { v[k] = __half2float(V.h[k]); m = fmaxf(m, v[k]); }
    #pragma unroll
    for (int o = 16; o; o >>= 1) m = fmaxf(m, __shfl_xor_sync(0xffffffffu, m, o));

    __shared__ float sm[8], ss[8];
    if (lane == 0) sm[w] = m;
    __syncthreads();
    float bm = sm[0];
    #pragma unroll
    for (int i = 1; i < 8; i++) bm = fmaxf(bm, sm[i]);

    float s = 0.f;
    #pragma unroll
    for (int k = 0; k < 8; k++) { v[k] = __expf(v[k] - bm); s += v[k]; }
    #pragma unroll
    for (int o = 16; o; o >>= 1) s += __shfl_xor_sync(0xffffffffu, s, o);
    if (lane == 0) ss[w] = s;
    __syncthreads();
    float bs = 0.f;
    #pragma unroll
    for (int i = 0; i < 8; i++) bs += ss[i];
    const float inv = 1.0f / bs;

    union { __half h[8]; uint4 u; } O;
    #pragma unroll
    for (int k = 0; k < 8; k += 4) {
        float r0 = v[k] * inv, r1 = v[k+1] * inv, r2 = v[k+2] * inv, r3 = v[k+3] * inv;
        *(float4*)(ao + t * 8 + k) = make_float4(r0, r1, r2, r3);
        O.h[k]   = __float2half_rn(r0);
        O.h[k+1] = __float2half_rn(r1);
        O.h[k+2] = __float2half_rn(r2);
        O.h[k+3] = __float2half_rn(r3);
    }
    *(uint4*)(p + t * 8) = O.u;
}

// ---------------------------------------------------------------------------
// weighted_output[r] = dot(ctx[r,:], W3[r % NL,:]) + b3[r % NL]  (all fp32)
// ---------------------------------------------------------------------------
__global__ __launch_bounds__(256) void weighted_out(
    const float* __restrict__ ctx, const float* __restrict__ W3,
    const float* __restrict__ b3, float* __restrict__ out)
{
    const int r = blockIdx.x * 8 + (threadIdx.x >> 5);
    const int lane = threadIdx.x & 31;
    const int n = r & (NLDIM - 1);
    const float* c = ctx + (size_t)r * DIM;
    const float* w = W3 + (size_t)n * DIM;
    float s = 0.f;
    #pragma unroll
    for (int j = 0; j < 4; j++) {
        float4 cv = *(const float4*)(c + lane * 4 + j * 128);
        float4 wv = *(const float4*)(w + lane * 4 + j * 128);
        s += cv.x * wv.x + cv.y * wv.y + cv.z * wv.z + cv.w * wv.w;
    }
    #pragma unroll
    for (int o = 16; o; o >>= 1) s += __shfl_xor_sync(0xffffffffu, s, o);
    if (lane == 0) out[r] = s + b3[n];
}

// ---------------------------------------------------------------------------
extern "C" void kernel_launch(void* const* d_in, const int* in_sizes, int n_in,
                              void* d_out, int out_size)
{
    const float* x  = (const float*)d_in[0];
    const float* W1 = (const float*)d_in[1];
    const float* W2 = (const float*)d_in[2];
    const float* W3 = (const float*)d_in[3];
    const float* b3 = (const float*)d_in[4];

    float* ctx = (float*)d_out;                       // [B, NL, D]
    float* wo  = ctx + (size_t)BATCH * NLDIM * DIM;   // [B, NL]
    float* att = wo + (size_t)BATCH * NLDIM;          // [B, NL, L]

    __half *xh, *wh, *ah, *w1h, *w2h;
    cudaGetSymbolAddress((void**)&xh, g_xh);
    cudaGetSymbolAddress((void**)&wh, g_wh);
    cudaGetSymbolAddress((void**)&ah, g_ah);
    cudaGetSymbolAddress((void**)&w1h, g_w1h);
    cudaGetSymbolAddress((void**)&w2h, g_w2h);

    cudaFuncSetAttribute(gemm_f16_nt, cudaFuncAttributeMaxDynamicSharedMemorySize, SMEM_NT);
    cudaFuncSetAttribute(gemm_f16_nn, cudaFuncAttributeMaxDynamicSharedMemorySize, SMEM_NN);

    // fp32 -> fp16 conversions (single launch)
    cvt_all<<<NXBLK + NW1BLK + NW2BLK, 256>>>(x, xh, W1, w1h, W2, w2h);

    // GEMM1 (NT): w = tanh(x @ W1^T) -> fp16 (tanh.approx epilogue)
    {
        dim3 g(DADIM / 128, (BATCH * SEQ) / 128, 1);
        gemm_f16_nt<<<g, 256, SMEM_NT>>>(xh, 0, w1h, 0,
                                         nullptr, wh, 0, DADIM, DIM, 1);
    }
    // GEMM2 (NT): logits[b,n,l] = W2 @ w[b]^T -> fp16 (mode 2)
    {
        dim3 g(SEQ / 128, NLDIM / 128, BATCH);
        gemm_f16_nt<<<g, 256, SMEM_NT>>>(w2h, 0,
                                         wh, (long long)SEQ * DADIM,
                                         nullptr, ah,
                                         (long long)NLDIM * SEQ, SEQ, DADIM, 2);
    }
    // softmax over L: fp16 logits in place -> normalized fp16 + fp32 att output
    softmax_h<<<BATCH * NLDIM, 256>>>(ah, att);

    // GEMM3 (NN): ctx[b,n,d] = att[b] @ x[b]; B = x row-major [L, D]
    {
        dim3 g(DIM / 128, NLDIM / 128, BATCH);
        gemm_f16_nn<<<g, 256, SMEM_NN>>>(ah, (long long)NLDIM * SEQ,
                                         xh, (long long)SEQ * DIM,
                                         ctx, (long long)NLDIM * DIM,
                                         DIM, DIM, SEQ);
    }
    // weighted output
    weighted_out<<<(BATCH * NLDIM) / 8, 256>>>(ctx, W3, b3, wo);
}

// round 14
// speedup vs baseline: 1.0232x; 1.0048x over previous
#include <cuda_runtime.h>
#include <cuda_fp16.h>
#include <math.h>
#include <stdint.h>

#define BATCH 32
#define SEQ   2048
#define DIM   512
#define DADIM 512
#define NLDIM 512

// ---------------- fp16 scratch (static, allocation-free) ----------------
__device__ __half g_xh [(size_t)BATCH * SEQ * DIM];
__device__ __half g_wh [(size_t)BATCH * SEQ * DADIM];  // tanh output
__device__ __half g_ah [(size_t)BATCH * NLDIM * SEQ];  // logits -> softmax (fp16)
__device__ __half g_w1h[DADIM * DIM];
__device__ __half g_w2h[NLDIM * DADIM];

// ---------------- PTX helpers (family-portable: no tcgen05) ----------
__device__ __forceinline__ uint32_t smem_u32(const void* p) {
    uint32_t a;
    asm("{ .reg .u64 t; cvta.to.shared.u64 t, %1; cvt.u32.u64 %0, t; }" : "=r"(a) : "l"(p));
    return a;
}
__device__ __forceinline__ void cp16(uint32_t saddr, const void* g) {
    asm volatile("cp.async.cg.shared.global [%0], [%1], 16;" :: "r"(saddr), "l"(g));
}
__device__ __forceinline__ void cp_commit() { asm volatile("cp.async.commit_group;"); }
__device__ __forceinline__ void cp_wait0()  { asm volatile("cp.async.wait_group 0;"); }
__device__ __forceinline__ void cp_wait2()  { asm volatile("cp.async.wait_group 2;"); }

__device__ __forceinline__ float tanh_ap(float x) {
    float r;
    asm("tanh.approx.f32 %0, %1;" : "=f"(r) : "f"(x));
    return r;
}

__device__ __forceinline__ void ldsm_x4(uint32_t& r0, uint32_t& r1, uint32_t& r2, uint32_t& r3,
                                        uint32_t addr) {
    asm volatile("ldmatrix.sync.aligned.m8n8.x4.shared.b16 {%0,%1,%2,%3}, [%4];"
                 : "=r"(r0), "=r"(r1), "=r"(r2), "=r"(r3) : "r"(addr));
}
__device__ __forceinline__ void ldsm_x4_t(uint32_t& r0, uint32_t& r1, uint32_t& r2, uint32_t& r3,
                                          uint32_t addr) {
    asm volatile("ldmatrix.sync.aligned.m8n8.x4.trans.shared.b16 {%0,%1,%2,%3}, [%4];"
                 : "=r"(r0), "=r"(r1), "=r"(r2), "=r"(r3) : "r"(addr));
}
__device__ __forceinline__ void mma16816(float& c0, float& c1, float& c2, float& c3,
                                         uint32_t a0, uint32_t a1, uint32_t a2, uint32_t a3,
                                         uint32_t b0, uint32_t b1) {
    asm volatile(
        "mma.sync.aligned.m16n8k16.row.col.f32.f16.f16.f32 "
        "{%0,%1,%2,%3}, {%4,%5,%6,%7}, {%8,%9}, {%0,%1,%2,%3};"
        : "+f"(c0), "+f"(c1), "+f"(c2), "+f"(c3)
        : "r"(a0), "r"(a1), "r"(a2), "r"(a3), "r"(b0), "r"(b1));
}

// tile geometry: CTA 128x128, BK=32, 256 thr, 8 warps (4M x 2N), warp 32x64,
// 4-stage ring (R5/R10-proven config, R10 mainloop byte-exact)
#define ROWB   80                 // A/B-NT smem row bytes (32 fp16 = 64 B + 16 pad)
#define ATILE  (128 * ROWB)       // 10240
#define BROWB  272                // NN B smem row bytes (128 fp16 = 256 B + 16 pad)
#define BTILE_NN (32 * BROWB)     // 8704
#define STG_NT (ATILE + ATILE)    // 20480
#define STG_NN (ATILE + BTILE_NN) // 18944
#define SMEM_NT (4 * STG_NT)      // 81920
#define SMEM_NN (4 * STG_NN)      // 75776

// ===========================================================================
// NT fp16 GEMM: C[m,n] = sum_k A[m,k]*B[n,k]
// mode 0: fp32 C.  mode 1: tanh.approx(acc) -> fp16 Ch.  mode 2: acc -> fp16 Ch.
// ===========================================================================
__global__ __launch_bounds__(256, 2) void gemm_f16_nt(
    const __half* __restrict__ A, long long sA,
    const __half* __restrict__ B, long long sB,
    float* __restrict__ C, __half* __restrict__ Ch,
    long long sC, int N, int K, int mode)
{
    extern __shared__ __align__(128) char smem[];
    const uint32_t s0 = smem_u32(smem);

    const int t = threadIdx.x;
    const int bz = blockIdx.z;
    const int m0 = blockIdx.y * 128;
    const int n0 = blockIdx.x * 128;

    const int lane = t & 31;
    const int wid  = t >> 5;
    const int wm   = wid & 3;
    const int wn   = wid >> 2;
    const int g    = lane >> 3;
    const int lr   = lane & 7;

    const uint32_t abase = (uint32_t)((wm * 32 + ((g & 1) << 3) + lr) * ROWB + ((g >> 1) << 4));
    const uint32_t bbase = (uint32_t)((wn * 64 + ((g >> 1) << 3) + lr) * ROWB + ((g & 1) << 4));

    // R5 loader: lanes 0-3 fetch 64 contiguous bytes of one row (full sectors)
    const int r0_ = t >> 2, s0_ = (t & 3);

    const __half* Ab = A + (size_t)bz * sA + (size_t)m0 * K;
    const __half* Bb = B + (size_t)bz * sB + (size_t)n0 * K;

    const int nch = K >> 5;

    float acc[2][8][4];
    #pragma unroll
    for (int i = 0; i < 2; i++)
        #pragma unroll
        for (int j = 0; j < 8; j++)
            #pragma unroll
            for (int q = 0; q < 4; q++) acc[i][j][q] = 0.f;

    auto load_chunk = [&](int c) {
        const int kk = c << 5;
        const uint32_t sa = s0 + (uint32_t)((c & 3) * STG_NT);
        const uint32_t sb = sa + ATILE;
        #pragma unroll
        for (int i = 0; i < 2; i++) {
            const int row = r0_ + i * 64;
            cp16(sa + (uint32_t)(row * ROWB + s0_ * 16), Ab + (size_t)row * K + kk + s0_ * 8);
        }
        #pragma unroll
        for (int i = 0; i < 2; i++) {
            const int row = r0_ + i * 64;
            cp16(sb + (uint32_t)(row * ROWB + s0_ * 16), Bb + (size_t)row * K + kk + s0_ * 8);
        }
        cp_commit();
    };

    load_chunk(0);
    load_chunk(1);
    load_chunk(2);

    for (int c = 0; c < nch; c++) {
        if (c + 2 < nch) cp_wait2(); else cp_wait0();
        __syncthreads();
        if (c + 3 < nch) load_chunk(c + 3);

        const uint32_t base = s0 + (uint32_t)((c & 3) * STG_NT);
        const uint32_t sa = base + abase;
        const uint32_t sb = base + ATILE + bbase;

        #pragma unroll
        for (int ks = 0; ks < 2; ks++) {
            uint32_t a[2][4];
            uint32_t b[4][4];
            #pragma unroll
            for (int mi = 0; mi < 2; mi++)
                ldsm_x4(a[mi][0], a[mi][1], a[mi][2], a[mi][3],
                        sa + (uint32_t)(mi * 16 * ROWB + ks * 32));
            #pragma unroll
            for (int p = 0; p < 4; p++)
                ldsm_x4(b[p][0], b[p][1], b[p][2], b[p][3],
                        sb + (uint32_t)(p * 16 * ROWB + ks * 32));
            #pragma unroll
            for (int mi = 0; mi < 2; mi++)
                #pragma unroll
                for (int j = 0; j < 8; j++) {
                    const int p = j >> 1, h = j & 1;
                    mma16816(acc[mi][j][0], acc[mi][j][1], acc[mi][j][2], acc[mi][j][3],
                             a[mi][0], a[mi][1], a[mi][2], a[mi][3],
                             b[p][h * 2], b[p][h * 2 + 1]);
                }
        }
    }

    const int rrow = lane >> 2;
    const int rcol = (lane & 3) * 2;
    #pragma unroll
    for (int mi = 0; mi < 2; mi++) {
        const int gr = m0 + wm * 32 + mi * 16 + rrow;
        #pragma unroll
        for (int j = 0; j < 8; j++) {
            const int gc = n0 + wn * 64 + j * 8 + rcol;
            const size_t o0 = (size_t)bz * sC + (size_t)gr * N + gc;
            const size_t o1 = o0 + (size_t)8 * N;
            if (mode == 0) {
                *(float2*)(C + o0) = make_float2(acc[mi][j][0], acc[mi][j][1]);
                *(float2*)(C + o1) = make_float2(acc[mi][j][2], acc[mi][j][3]);
            } else if (mode == 1) {
                union { __half h[2]; uint32_t u; } P0, P1;
                P0.h[0] = __float2half_rn(tanh_ap(acc[mi][j][0]));
                P0.h[1] = __float2half_rn(tanh_ap(acc[mi][j][1]));
                P1.h[0] = __float2half_rn(tanh_ap(acc[mi][j][2]));
                P1.h[1] = __float2half_rn(tanh_ap(acc[mi][j][3]));
                *(uint32_t*)(Ch + o0) = P0.u;
                *(uint32_t*)(Ch + o1) = P1.u;
            } else {
                union { __half h[2]; uint32_t u; } P0, P1;
                P0.h[0] = __float2half_rn(acc[mi][j][0]);
                P0.h[1] = __float2half_rn(acc[mi][j][1]);
                P1.h[0] = __float2half_rn(acc[mi][j][2]);
                P1.h[1] = __float2half_rn(acc[mi][j][3]);
                *(uint32_t*)(Ch + o0) = P0.u;
                *(uint32_t*)(Ch + o1) = P1.u;
            }
        }
    }
}

// ===========================================================================
// NN fp16 GEMM: C[m,n] = sum_k A[m,k]*B[k,n]; B row-major [K, NB] via
// ldmatrix.trans. fp32 output. (R10 mainloop byte-exact)
// ===========================================================================
__global__ __launch_bounds__(256, 2) void gemm_f16_nn(
    const __half* __restrict__ A, long long sA,
    const __half* __restrict__ B, long long sB,
    float* __restrict__ C, long long sC, int N, int NB, int K)
{
    extern __shared__ __align__(128) char smem[];
    const uint32_t s0 = smem_u32(smem);

    const int t = threadIdx.x;
    const int bz = blockIdx.z;
    const int m0 = blockIdx.y * 128;
    const int n0 = blockIdx.x * 128;

    const int lane = t & 31;
    const int wid  = t >> 5;
    const int wm   = wid & 3;
    const int wn   = wid >> 2;
    const int g    = lane >> 3;
    const int lr   = lane & 7;

    const uint32_t abase = (uint32_t)((wm * 32 + ((g & 1) << 3) + lr) * ROWB + ((g >> 1) << 4));
    const uint32_t bbase = (uint32_t)(((g & 1) * 8 + lr) * BROWB + (wn * 64 + (g >> 1) * 8) * 2);

    const int ar_ = t >> 2, ac_ = (t & 3);   // A loader (R5)
    const int br_ = t >> 4, bc_ = (t & 15);  // B loader (R5)

    const __half* Ab = A + (size_t)bz * sA + (size_t)m0 * K;
    const __half* Bb = B + (size_t)bz * sB + n0;

    const int nch = K >> 5;

    float acc[2][8][4];
    #pragma unroll
    for (int i = 0; i < 2; i++)
        #pragma unroll
        for (int j = 0; j < 8; j++)
            #pragma unroll
            for (int q = 0; q < 4; q++) acc[i][j][q] = 0.f;

    auto load_chunk = [&](int c) {
        const int kk = c << 5;
        const uint32_t sa = s0 + (uint32_t)((c & 3) * STG_NN);
        const uint32_t sb = sa + ATILE;
        #pragma unroll
        for (int i = 0; i < 2; i++) {
            const int row = ar_ + i * 64;
            cp16(sa + (uint32_t)(row * ROWB + ac_ * 16), Ab + (size_t)row * K + kk + ac_ * 8);
        }
        #pragma unroll
        for (int i = 0; i < 2; i++) {
            const int row = br_ + i * 16;
            cp16(sb + (uint32_t)(row * BROWB + bc_ * 16),
                 Bb + (size_t)(kk + row) * NB + bc_ * 8);
        }
        cp_commit();
    };

    load_chunk(0);
    load_chunk(1);
    load_chunk(2);

    for (int c = 0; c < nch; c++) {
        if (c + 2 < nch) cp_wait2(); else cp_wait0();
        __syncthreads();
        if (c + 3 < nch) load_chunk(c + 3);

        const uint32_t base = s0 + (uint32_t)((c & 3) * STG_NN);
        const uint32_t sa = base + abase;
        const uint32_t sb = base + ATILE + bbase;

        #pragma unroll
        for (int ks = 0; ks < 2; ks++) {
            uint32_t a[2][4];
            uint32_t b[4][4];
            #pragma unroll
            for (int mi = 0; mi < 2; mi++)
                ldsm_x4(a[mi][0], a[mi][1], a[mi][2], a[mi][3],
                        sa + (uint32_t)(mi * 16 * ROWB + ks * 32));
            #pragma unroll
            for (int p = 0; p < 4; p++)
                ldsm_x4_t(b[p][0], b[p][1], b[p][2], b[p][3],
                          sb + (uint32_t)(ks * 16 * BROWB + p * 32));
            #pragma unroll
            for (int mi = 0; mi < 2; mi++)
                #pragma unroll
                for (int j = 0; j < 8; j++) {
                    const int p = j >> 1, h = j & 1;
                    mma16816(acc[mi][j][0], acc[mi][j][1], acc[mi][j][2], acc[mi][j][3],
                             a[mi][0], a[mi][1], a[mi][2], a[mi][3],
                             b[p][h * 2], b[p][h * 2 + 1]);
                }
        }
    }

    const int rrow = lane >> 2;
    const int rcol = (lane & 3) * 2;
    #pragma unroll
    for (int mi = 0; mi < 2; mi++) {
        const int gr = m0 + wm * 32 + mi * 16 + rrow;
        #pragma unroll
        for (int j = 0; j < 8; j++) {
            const int gc = n0 + wn * 64 + j * 8 + rcol;
            const size_t o0 = (size_t)bz * sC + (size_t)gr * N + gc;
            const size_t o1 = o0 + (size_t)8 * N;
            *(float2*)(C + o0) = make_float2(acc[mi][j][0], acc[mi][j][1]);
            *(float2*)(C + o1) = make_float2(acc[mi][j][2], acc[mi][j][3]);
        }
    }
}

// ---------------------------------------------------------------------------
// elementwise fp32 -> fp16: x, W1, W2 in a single grid.
// ---------------------------------------------------------------------------
#define NXBLK  ((BATCH * SEQ * DIM) / 1024)
#define NW1BLK ((DADIM * DIM) / 1024)
#define NW2BLK ((NLDIM * DADIM) / 1024)
__global__ __launch_bounds__(256) void cvt_all(
    const float* __restrict__ x, __half* __restrict__ xh,
    const float* __restrict__ W1, __half* __restrict__ w1h,
    const float* __restrict__ W2, __half* __restrict__ w2h)
{
    const float* s; __half* h; size_t i;
    int blk = blockIdx.x;
    if (blk < NXBLK)               { s = x;  h = xh;  i = (size_t)blk; }
    else if (blk < NXBLK + NW1BLK) { s = W1; h = w1h; i = (size_t)(blk - NXBLK); }
    else                           { s = W2; h = w2h; i = (size_t)(blk - NXBLK - NW1BLK); }
    i = (i * 256 + threadIdx.x) * 4;
    float4 v = *(const float4*)(s + i);
    union { __half h[4]; uint2 u; } H;
    H.h[0] = __float2half_rn(v.x);
    H.h[1] = __float2half_rn(v.y);
    H.h[2] = __float2half_rn(v.z);
    H.h[3] = __float2half_rn(v.w);
    *(uint2*)(h + i) = H.u;
}

// ---------------------------------------------------------------------------
// warp-per-row softmax over 2048 fp16 logits: in-place fp16 + fp32 att out.
// 8 warps/block, one row per warp, no barriers. Lane owns 8 coalesced uint4
// chunks (lane*16B + k*512B).
// ---------------------------------------------------------------------------
__global__ __launch_bounds__(256) void softmax_w(
    __half* __restrict__ lg, float* __restrict__ att)
{
    const int warp = threadIdx.x >> 5;
    const int lane = threadIdx.x & 31;
    const size_t row = (size_t)blockIdx.x * 8 + warp;
    __half* p = lg + row * SEQ;
    float* ao = att + row * SEQ;

    // load 64 fp16 per lane (8 x uint4, coalesced)
    union { __half h[8]; uint4 u; } d[8];
    #pragma unroll
    for (int k = 0; k < 8; k++)
        d[k].u = *(const uint4*)(p + lane * 8 + (size_t)k * 256);

    // max
    float m = -1e30f;
    #pragma unroll
    for (int k = 0; k < 8; k++)
        #pragma unroll
        for (int j = 0; j < 8; j++)
            m = fmaxf(m, __half2float(d[k].h[j]));
    #pragma unroll
    for (int o = 16; o; o >>= 1) m = fmaxf(m, __shfl_xor_sync(0xffffffffu, m, o));

    // exp + sum
    float e[8][8];
    float s = 0.f;
    #pragma unroll
    for (int k = 0; k < 8; k++)
        #pragma unroll
        for (int j = 0; j < 8; j++) {
            float v = __expf(__half2float(d[k].h[j]) - m);
            e[k][j] = v;
            s += v;
        }
    #pragma unroll
    for (int o = 16; o; o >>= 1) s += __shfl_xor_sync(0xffffffffu, s, o);
    const float inv = 1.0f / s;

    // store fp32 att + normalized fp16 in place
    #pragma unroll
    for (int k = 0; k < 8; k++) {
        float r0 = e[k][0] * inv, r1 = e[k][1] * inv, r2 = e[k][2] * inv, r3 = e[k][3] * inv;
        float r4 = e[k][4] * inv, r5 = e[k][5] * inv, r6 = e[k][6] * inv, r7 = e[k][7] * inv;
        float* a = ao + lane * 8 + (size_t)k * 256;
        *(float4*)(a)     = make_float4(r0, r1, r2, r3);
        *(float4*)(a + 4) = make_float4(r4, r5, r6, r7);
        union { __half h[8]; uint4 u; } O;
        O.h[0] = __float2half_rn(r0); O.h[1] = __float2half_rn(r1);
        O.h[2] = __float2half_rn(r2); O.h[3] = __float2half_rn(r3);
        O.h[4] = __float2half_rn(r4); O.h[5] = __float2half_rn(r5);
        O.h[6] = __float2half_rn(r6); O.h[7] = __float2half_rn(r7);
        *(uint4*)(p + lane * 8 + (size_t)k * 256) = O.u;
    }
}

// ---------------------------------------------------------------------------
// weighted_output[r] = dot(ctx[r,:], W3[r % NL,:]) + b3[r % NL]  (all fp32)
// ---------------------------------------------------------------------------
__global__ __launch_bounds__(256) void weighted_out(
    const float* __restrict__ ctx, const float* __restrict__ W3,
    const float* __restrict__ b3, float* __restrict__ out)
{
    const int r = blockIdx.x * 8 + (threadIdx.x >> 5);
    const int lane = threadIdx.x & 31;
    const int n = r & (NLDIM - 1);
    const float* c = ctx + (size_t)r * DIM;
    const float* w = W3 + (size_t)n * DIM;
    float s = 0.f;
    #pragma unroll
    for (int j = 0; j < 4; j++) {
        float4 cv = *(const float4*)(c + lane * 4 + j * 128);
        float4 wv = *(const float4*)(w + lane * 4 + j * 128);
        s += cv.x * wv.x + cv.y * wv.y + cv.z * wv.z + cv.w * wv.w;
    }
    #pragma unroll
    for (int o = 16; o; o >>= 1) s += __shfl_xor_sync(0xffffffffu, s, o);
    if (lane == 0) out[r] = s + b3[n];
}

// ---------------------------------------------------------------------------
extern "C" void kernel_launch(void* const* d_in, const int* in_sizes, int n_in,
                              void* d_out, int out_size)
{
    const float* x  = (const float*)d_in[0];
    const float* W1 = (const float*)d_in[1];
    const float* W2 = (const float*)d_in[2];
    const float* W3 = (const float*)d_in[3];
    const float* b3 = (const float*)d_in[4];

    float* ctx = (float*)d_out;                       // [B, NL, D]
    float* wo  = ctx + (size_t)BATCH * NLDIM * DIM;   // [B, NL]
    float* att = wo + (size_t)BATCH * NLDIM;          // [B, NL, L]

    __half *xh, *wh, *ah, *w1h, *w2h;
    cudaGetSymbolAddress((void**)&xh, g_xh);
    cudaGetSymbolAddress((void**)&wh, g_wh);
    cudaGetSymbolAddress((void**)&ah, g_ah);
    cudaGetSymbolAddress((void**)&w1h, g_w1h);
    cudaGetSymbolAddress((void**)&w2h, g_w2h);

    cudaFuncSetAttribute(gemm_f16_nt, cudaFuncAttributeMaxDynamicSharedMemorySize, SMEM_NT);
    cudaFuncSetAttribute(gemm_f16_nn, cudaFuncAttributeMaxDynamicSharedMemorySize, SMEM_NN);

    // fp32 -> fp16 conversions (single launch)
    cvt_all<<<NXBLK + NW1BLK + NW2BLK, 256>>>(x, xh, W1, w1h, W2, w2h);

    // GEMM1 (NT): w = tanh(x @ W1^T) -> fp16 (tanh.approx epilogue)
    {
        dim3 g(DADIM / 128, (BATCH * SEQ) / 128, 1);
        gemm_f16_nt<<<g, 256, SMEM_NT>>>(xh, 0, w1h, 0,
                                         nullptr, wh, 0, DADIM, DIM, 1);
    }
    // GEMM2 (NT): logits[b,n,l] = W2 @ w[b]^T -> fp16 (mode 2)
    {
        dim3 g(SEQ / 128, NLDIM / 128, BATCH);
        gemm_f16_nt<<<g, 256, SMEM_NT>>>(w2h, 0,
                                         wh, (long long)SEQ * DADIM,
                                         nullptr, ah,
                                         (long long)NLDIM * SEQ, SEQ, DADIM, 2);
    }
    // softmax over L (warp-per-row): fp16 in place + fp32 att output
    softmax_w<<<(BATCH * NLDIM) / 8, 256>>>(ah, att);

    // GEMM3 (NN): ctx[b,n,d] = att[b] @ x[b]; B = x row-major [L, D]
    {
        dim3 g(DIM / 128, NLDIM / 128, BATCH);
        gemm_f16_nn<<<g, 256, SMEM_NN>>>(ah, (long long)NLDIM * SEQ,
                                         xh, (long long)SEQ * DIM,
                                         ctx, (long long)NLDIM * DIM,
                                         DIM, DIM, SEQ);
    }
    // weighted output
    weighted_out<<<(BATCH * NLDIM) / 8, 256>>>(ctx, W3, b3, wo);
}